// round 13
// baseline (speedup 1.0000x reference)
#include <cuda_runtime.h>
#include <cuda_bf16.h>
#include <math.h>

// GLIF recurrence, T=4. Single fused kernel, contiguous-row decomposition:
// grid = 2048 x 256 threads; block b owns 16 consecutive rows = 64 KiB
// contiguous. Iteration i processes row i (4 KiB block-wide coalesced,
// address = single base + immediate offset). The 16 rows are 16 consecutive
// channels; params computed warp-parallel (128 lanes, one sigmoid each) into
// a scalar smem table; per-row constants are broadcast LDS.
// Scalar recurrence, ordering bit-identical to the reference.
//
// x: (B=16, PLANE=2048, L=1024) fp32. out: final spike map, fp32 {0,1}.

#define GLIF_T       4
#define GLIF_PLANE   2048
#define GLIF_L       1024
#define ROWS_PER_BLK 16

__global__ void __launch_bounds__(256) glif_kernel(
    const float* __restrict__ x,
    const float* __restrict__ alpha,
    const float* __restrict__ beta,
    const float* __restrict__ gamma,
    const float* __restrict__ tau,
    const float* __restrict__ Vth,
    const float* __restrict__ leak,
    const float* __restrict__ reVth,
    const float* __restrict__ conduct,
    float* __restrict__ out)
{
    // Per-channel constants for this block's 16 channels.
    // Slots: 0=A 1=omg 2=negLk 3=negR 4=vth 5..8=s0..s3
    __shared__ float spf[ROWS_PER_BLK][9];

    const int tid = threadIdx.x;
    const int r0  = blockIdx.x * ROWS_PER_BLK;      // first global row
    const int c0  = r0 & (GLIF_PLANE - 1);          // first channel (16 rows never cross b)

    const unsigned b4 = (unsigned)r0 * (GLIF_L / 4) + tid;   // 32-bit float4 index
    const float4* xp = reinterpret_cast<const float4*>(x)  + b4;
    float4*       op = reinterpret_cast<float4*>(out)      + b4;

    // ---- prefetch chunk 0 (rows 0..3), immediate offsets ----
    float4 xv[4];
#pragma unroll
    for (int u = 0; u < 4; ++u)
        xv[u] = __ldcs(xp + u * 256);

    // ---- params: 128 lanes, one sigmoid each (16 channels x 8 params) ----
    if (tid < 128) {
        const int ch   = tid >> 3;        // 0..15
        const int pidx = tid & 7;         // 0..7
        const int c    = c0 + ch;

        const float al = (__ldg(&alpha[c]) > 0.0f) ? 1.0f : 0.0f;  // arch_act(sigmoid)==(p>0)
        const float be = (__ldg(&beta[c])  > 0.0f) ? 1.0f : 0.0f;
        const float ga = (__ldg(&gamma[c]) > 0.0f) ? 1.0f : 0.0f;

        float v;
        if      (pidx == 0) v = __ldg(&tau[c]);
        else if (pidx == 1) v = __ldg(&Vth[c]);
        else if (pidx == 2) v = __ldg(&leak[c]);
        else if (pidx == 3) v = __ldg(&reVth[c]);
        else                v = __ldg(&conduct[(pidx - 4) * GLIF_PLANE + c]);

        const float sig = 1.0f / (1.0f + expf(-v));

        float r;
        int slot;
        if (pidx == 0) {
            r = 1.0f - al * (1.0f - sig);  slot = 0;            // A
            spf[ch][1] = 1.0f - ga;                             // omg
        } else if (pidx == 1) {
            r = sig;                       slot = 4;            // vth
        } else if (pidx == 2) {
            r = -((1.0f - al) * sig);      slot = 2;            // negLk
        } else if (pidx == 3) {
            r = -((1.0f - ga) * sig);      slot = 3;            // negR
        } else {
            r = 1.0f - be * (1.0f - sig);  slot = 5 + (pidx - 4);  // s_t
        }
        spf[ch][slot] = r;
    }
    __syncthreads();

    // ---- 16 rows, double-buffered in chunks of 4 ----
#pragma unroll
    for (int chunk = 0; chunk < 4; ++chunk) {
        float4 nv[4];
        if (chunk < 3) {
#pragma unroll
            for (int u = 0; u < 4; ++u)
                nv[u] = __ldcs(xp + ((chunk + 1) * 4 + u) * 256);
        }

#pragma unroll
        for (int u = 0; u < 4; ++u) {
            const int i = chunk * 4 + u;            // row index within block
            const float A     = spf[i][0];
            const float omg   = spf[i][1];
            const float negLk = spf[i][2];
            const float negR  = spf[i][3];
            const float vth   = spf[i][4];
            const float s0    = spf[i][5];
            const float sv[3] = {spf[i][6], spf[i][7], spf[i][8]};

            const float4 xq = xv[u];
            float xl[4] = {xq.x, xq.y, xq.z, xq.w};
            float ov[4];

#pragma unroll
            for (int j = 0; j < 4; ++j) {
                const float xj = xl[j];
                // t=0: u=0, o=0 -> u1 = x*s0 - Lk
                float uu = fmaf(xj, s0, negLk);
                bool  o  = (uu > vth);
#pragma unroll
                for (int t = 0; t < 3; ++t) {
                    // reference order: ((A*u)*(1-ga*o) - Lk) + x*s - R*o
                    const float g = o ? omg : 1.0f;
                    float m = (A * uu) * g;
                    m = m + negLk;
                    m = fmaf(xj, sv[t], m);
                    if (o) m = m + negR;
                    o = (m > vth);
                    uu = m;
                }
                ov[j] = o ? 1.0f : 0.0f;
            }

            float4 res;
            res.x = ov[0]; res.y = ov[1]; res.z = ov[2]; res.w = ov[3];
            __stcs(op + i * 256, res);
        }

#pragma unroll
        for (int u = 0; u < 4; ++u) xv[u] = nv[u];
    }
}

extern "C" void kernel_launch(void* const* d_in, const int* in_sizes, int n_in,
                              void* d_out, int out_size) {
    const float* x       = (const float*)d_in[0];
    const float* alpha   = (const float*)d_in[1];
    const float* beta    = (const float*)d_in[2];
    const float* gamma   = (const float*)d_in[3];
    const float* tau     = (const float*)d_in[4];
    const float* Vth     = (const float*)d_in[5];
    const float* leak    = (const float*)d_in[6];
    const float* reVth   = (const float*)d_in[7];
    const float* conduct = (const float*)d_in[8];
    float* out = (float*)d_out;

    const int n_blk = out_size / (GLIF_L * ROWS_PER_BLK);   // 2048
    glif_kernel<<<n_blk, 256>>>(x, alpha, beta, gamma, tau, Vth,
                                leak, reVth, conduct, out);
}

// round 14
// speedup vs baseline: 1.0428x; 1.0428x over previous
#include <cuda_runtime.h>
#include <cuda_bf16.h>
#include <math.h>

// GLIF recurrence, T=4. Single fused kernel, one block per channel
// (grid=2048, 256 threads), 16 batches/block, 4-deep register double-buffer.
// Per-channel params are computed WARP-LOCALLY: lanes 0-7 of every warp each
// run one sigmoid, results broadcast via __shfl_sync. No shared memory, no
// __syncthreads -> no cross-warp serialization; each warp's param chain
// overlaps its own prefetch loads.
//
// x: (B=16, PLANE=2048, L=1024) fp32. out: final spike map, fp32 {0,1}.

#define GLIF_T     4
#define GLIF_PLANE 2048
#define GLIF_L     1024
#define GLIF_B     16

__global__ void __launch_bounds__(256) glif_kernel(
    const float* __restrict__ x,
    const float* __restrict__ alpha,
    const float* __restrict__ beta,
    const float* __restrict__ gamma,
    const float* __restrict__ tau,
    const float* __restrict__ Vth,
    const float* __restrict__ leak,
    const float* __restrict__ reVth,
    const float* __restrict__ conduct,
    float* __restrict__ out)
{
    const int c    = blockIdx.x;              // channel
    const int tid  = threadIdx.x;
    const int lane = tid & 31;

    const unsigned row4  = GLIF_PLANE * (GLIF_L / 4);    // float4 per batch
    const unsigned base4 = (unsigned)c * (GLIF_L / 4) + tid;
    const float4* xp = reinterpret_cast<const float4*>(x) + base4;
    float4*       op = reinterpret_cast<float4*>(out) + base4;

    // ---- prefetch chunk 0 (batches 0..3) ----
    float4 xv[4];
#pragma unroll
    for (int u = 0; u < 4; ++u)
        xv[u] = __ldcs(xp + u * row4);

    // ---- warp-local params: lanes 0-7 one sigmoid each, then shfl ----
    const float al = (__ldg(&alpha[c]) > 0.0f) ? 1.0f : 0.0f;  // arch_act(sigmoid)==(p>0)
    const float be = (__ldg(&beta[c])  > 0.0f) ? 1.0f : 0.0f;
    const float ga = (__ldg(&gamma[c]) > 0.0f) ? 1.0f : 0.0f;

    float v = 0.0f;
    if      (lane == 0) v = __ldg(&tau[c]);
    else if (lane == 1) v = __ldg(&Vth[c]);
    else if (lane == 2) v = __ldg(&leak[c]);
    else if (lane == 3) v = __ldg(&reVth[c]);
    else if (lane >= 4 && lane < 8) v = __ldg(&conduct[(lane - 4) * GLIF_PLANE + c]);

    const float sig = 1.0f / (1.0f + expf(-v));

    // Derive per-lane result before broadcast (cheap, predicated).
    float r = sig;
    if      (lane == 0) r = 1.0f - al * (1.0f - sig);          // A
    else if (lane == 2) r = -((1.0f - al) * sig);              // negLk
    else if (lane == 3) r = -((1.0f - ga) * sig);              // negR
    else if (lane >= 4 && lane < 8) r = 1.0f - be * (1.0f - sig);  // s_t
    // lane 1 keeps sig (vth)

    const float A     = __shfl_sync(0xffffffffu, r, 0);
    const float vth   = __shfl_sync(0xffffffffu, r, 1);
    const float negLk = __shfl_sync(0xffffffffu, r, 2);
    const float negR  = __shfl_sync(0xffffffffu, r, 3);
    const float s0    = __shfl_sync(0xffffffffu, r, 4);
    float sv[3];
    sv[0] = __shfl_sync(0xffffffffu, r, 5);
    sv[1] = __shfl_sync(0xffffffffu, r, 6);
    sv[2] = __shfl_sync(0xffffffffu, r, 7);
    const float omg = 1.0f - ga;

    // ---- stream 16 batches, double-buffered in chunks of 4 ----
#pragma unroll
    for (int chunk = 0; chunk < 4; ++chunk) {
        float4 nv[4];
        if (chunk < 3) {
#pragma unroll
            for (int u = 0; u < 4; ++u)
                nv[u] = __ldcs(xp + ((chunk + 1) * 4 + u) * row4);
        }

#pragma unroll
        for (int u = 0; u < 4; ++u) {
            const float4 xq = xv[u];
            float xl[4] = {xq.x, xq.y, xq.z, xq.w};
            float ov[4];
#pragma unroll
            for (int j = 0; j < 4; ++j) {
                const float xj = xl[j];
                // t=0: u=0, o=0 -> u1 = x*s0 - Lk
                float uu = fmaf(xj, s0, negLk);
                bool  o  = (uu > vth);
#pragma unroll
                for (int t = 0; t < 3; ++t) {
                    // reference order: ((A*u)*(1-ga*o) - Lk) + x*s - R*o
                    const float g = o ? omg : 1.0f;
                    float m = (A * uu) * g;
                    m = m + negLk;
                    m = fmaf(xj, sv[t], m);
                    if (o) m = m + negR;
                    o = (m > vth);
                    uu = m;
                }
                ov[j] = o ? 1.0f : 0.0f;
            }
            float4 res;
            res.x = ov[0]; res.y = ov[1]; res.z = ov[2]; res.w = ov[3];
            __stcs(op + (chunk * 4 + u) * row4, res);
        }

#pragma unroll
        for (int u = 0; u < 4; ++u) xv[u] = nv[u];
    }
}

extern "C" void kernel_launch(void* const* d_in, const int* in_sizes, int n_in,
                              void* d_out, int out_size) {
    const float* x       = (const float*)d_in[0];
    const float* alpha   = (const float*)d_in[1];
    const float* beta    = (const float*)d_in[2];
    const float* gamma   = (const float*)d_in[3];
    const float* tau     = (const float*)d_in[4];
    const float* Vth     = (const float*)d_in[5];
    const float* leak    = (const float*)d_in[6];
    const float* reVth   = (const float*)d_in[7];
    const float* conduct = (const float*)d_in[8];
    float* out = (float*)d_out;

    glif_kernel<<<GLIF_PLANE, 256>>>(x, alpha, beta, gamma, tau, Vth,
                                     leak, reVth, conduct, out);
}

// round 15
// speedup vs baseline: 1.0435x; 1.0007x over previous
#include <cuda_runtime.h>
#include <cuda_bf16.h>
#include <math.h>

// GLIF recurrence, T=4. Single fused kernel, barrier-free.
// Grid = 4096: block = (channel, half); each block streams 8 batches of one
// channel (32 KiB R + 32 KiB W) -> 4.6 fine waves, small ragged tail.
// Per-channel params computed WARP-LOCALLY (lanes 0-7 one sigmoid each,
// broadcast via __shfl_sync) -> no smem, no __syncthreads.
// 4-deep register double-buffer: prefetch 4, process 4, prefetch 4, process 4.
//
// x: (B=16, PLANE=2048, L=1024) fp32. out: final spike map, fp32 {0,1}.

#define GLIF_T        4
#define GLIF_PLANE    2048
#define GLIF_L        1024
#define GLIF_B        16
#define BATCH_PER_BLK 8

__global__ void __launch_bounds__(256) glif_kernel(
    const float* __restrict__ x,
    const float* __restrict__ alpha,
    const float* __restrict__ beta,
    const float* __restrict__ gamma,
    const float* __restrict__ tau,
    const float* __restrict__ Vth,
    const float* __restrict__ leak,
    const float* __restrict__ reVth,
    const float* __restrict__ conduct,
    float* __restrict__ out)
{
    const int c    = blockIdx.x >> 1;          // channel
    const int half = blockIdx.x & 1;           // batches [half*8, half*8+8)
    const int tid  = threadIdx.x;
    const int lane = tid & 31;

    const unsigned row4  = GLIF_PLANE * (GLIF_L / 4);    // float4 per batch
    const unsigned base4 = (unsigned)(half * BATCH_PER_BLK) * row4
                         + (unsigned)c * (GLIF_L / 4) + tid;
    const float4* xp = reinterpret_cast<const float4*>(x) + base4;
    float4*       op = reinterpret_cast<float4*>(out) + base4;

    // ---- prefetch chunk 0 (batches 0..3 of this half) ----
    float4 xv[4];
#pragma unroll
    for (int u = 0; u < 4; ++u)
        xv[u] = __ldcs(xp + u * row4);

    // ---- warp-local params: lanes 0-7 one sigmoid each, then shfl ----
    const float al = (__ldg(&alpha[c]) > 0.0f) ? 1.0f : 0.0f;  // arch_act(sigmoid)==(p>0)
    const float be = (__ldg(&beta[c])  > 0.0f) ? 1.0f : 0.0f;
    const float ga = (__ldg(&gamma[c]) > 0.0f) ? 1.0f : 0.0f;

    float v = 0.0f;
    if      (lane == 0) v = __ldg(&tau[c]);
    else if (lane == 1) v = __ldg(&Vth[c]);
    else if (lane == 2) v = __ldg(&leak[c]);
    else if (lane == 3) v = __ldg(&reVth[c]);
    else if (lane >= 4 && lane < 8) v = __ldg(&conduct[(lane - 4) * GLIF_PLANE + c]);

    const float sig = 1.0f / (1.0f + expf(-v));

    float r = sig;                                              // lane 1: vth
    if      (lane == 0) r = 1.0f - al * (1.0f - sig);           // A
    else if (lane == 2) r = -((1.0f - al) * sig);               // negLk
    else if (lane == 3) r = -((1.0f - ga) * sig);               // negR
    else if (lane >= 4 && lane < 8) r = 1.0f - be * (1.0f - sig);  // s_t

    const float A     = __shfl_sync(0xffffffffu, r, 0);
    const float vth   = __shfl_sync(0xffffffffu, r, 1);
    const float negLk = __shfl_sync(0xffffffffu, r, 2);
    const float negR  = __shfl_sync(0xffffffffu, r, 3);
    const float s0    = __shfl_sync(0xffffffffu, r, 4);
    float sv[3];
    sv[0] = __shfl_sync(0xffffffffu, r, 5);
    sv[1] = __shfl_sync(0xffffffffu, r, 6);
    sv[2] = __shfl_sync(0xffffffffu, r, 7);
    const float omg = 1.0f - ga;

    // ---- stream 8 batches, double-buffered in chunks of 4 ----
#pragma unroll
    for (int chunk = 0; chunk < 2; ++chunk) {
        float4 nv[4];
        if (chunk < 1) {
#pragma unroll
            for (int u = 0; u < 4; ++u)
                nv[u] = __ldcs(xp + (4 + u) * row4);
        }

#pragma unroll
        for (int u = 0; u < 4; ++u) {
            const float4 xq = xv[u];
            float xl[4] = {xq.x, xq.y, xq.z, xq.w};
            float ov[4];
#pragma unroll
            for (int j = 0; j < 4; ++j) {
                const float xj = xl[j];
                // t=0: u=0, o=0 -> u1 = x*s0 - Lk
                float uu = fmaf(xj, s0, negLk);
                bool  o  = (uu > vth);
#pragma unroll
                for (int t = 0; t < 3; ++t) {
                    // reference order: ((A*u)*(1-ga*o) - Lk) + x*s - R*o
                    const float g = o ? omg : 1.0f;
                    float m = (A * uu) * g;
                    m = m + negLk;
                    m = fmaf(xj, sv[t], m);
                    if (o) m = m + negR;
                    o = (m > vth);
                    uu = m;
                }
                ov[j] = o ? 1.0f : 0.0f;
            }
            float4 res;
            res.x = ov[0]; res.y = ov[1]; res.z = ov[2]; res.w = ov[3];
            __stcs(op + (chunk * 4 + u) * row4, res);
        }

#pragma unroll
        for (int u = 0; u < 4; ++u) xv[u] = nv[u];
    }
}

extern "C" void kernel_launch(void* const* d_in, const int* in_sizes, int n_in,
                              void* d_out, int out_size) {
    const float* x       = (const float*)d_in[0];
    const float* alpha   = (const float*)d_in[1];
    const float* beta    = (const float*)d_in[2];
    const float* gamma   = (const float*)d_in[3];
    const float* tau     = (const float*)d_in[4];
    const float* Vth     = (const float*)d_in[5];
    const float* leak    = (const float*)d_in[6];
    const float* reVth   = (const float*)d_in[7];
    const float* conduct = (const float*)d_in[8];
    float* out = (float*)d_out;

    const int n_blk = out_size / (GLIF_L * BATCH_PER_BLK);   // 4096
    glif_kernel<<<n_blk, 256>>>(x, alpha, beta, gamma, tau, Vth,
                                leak, reVth, conduct, out);
}